// round 12
// baseline (speedup 1.0000x reference)
#include <cuda_runtime.h>
#include <cstdint>

// CapsNet dynamic routing, B=64, IC=2048, ID=8, OC=32, OD=16, 3 routing iters.
// R12 = resubmit of R11 (infra failure, never ran):
//       R9 pass kernel (proven 34us/pass) + R10 reduce_squash (proven 6.8us)
//       + split agreement accumulators (register-only ILP change).

#define B_      64
#define IC_     2048
#define ID_     8
#define OC_     32
#define OD_     16
#define TI_     4              // i's per smem chunk
#define NCH_    (IC_ / TI_)    // 512 chunks
#define GX_     74             // i-stripe blocks; grid (74,2) = 148 = one wave
#define GXP_    76             // padded stripe count (74,75 stay zero)
#define THREADS_ 256
#define JP_     8              // j pairs
#define BOD_    (B_ * OC_ * OD_)   // 32768
#define WROW_   265            // float2 stride per (il,d): 8*33+1

typedef unsigned long long u64t;

// ---- device scratch (allocation-free; zero-initialized) ----
__device__ float g_b[B_ * IC_ * OC_];              // routing logits (16.7MB)
__device__ float g_spart[GXP_ * BOD_];             // per-stripe partial s (9.96MB)
__device__ float g_v2[B_ * JP_ * OC_ * 2];         // v j-paired [b][jp][o]{j0,j1}

// ---- shared memory layout (bytes) ----
#define WBUF_F2   (TI_ * ID_ * WROW_)              // 8480 float2 = 67840 B per buffer
#define WS_BYTES  (2 * WBUF_F2 * 8)                // 135680
#define XBUF_F    (32 * TI_ * ID_)                 // 1024 floats per buffer
#define XS_BYTES  (2 * XBUF_F * 4)                 // 8192
#define VS_F2     (32 * JP_ * OC_)                 // 8192 float2 = 65536 B
#define SMEM_BYTES (WS_BYTES + XS_BYTES + VS_F2 * 8)   // 209408

// ---- f32x2 helpers ----
__device__ __forceinline__ u64t pack2(float lo, float hi) {
    u64t r; asm("mov.b64 %0, {%1, %2};" : "=l"(r) : "f"(lo), "f"(hi)); return r;
}
__device__ __forceinline__ void unpack2(u64t p, float& lo, float& hi) {
    asm("mov.b64 {%0, %1}, %2;" : "=f"(lo), "=f"(hi) : "l"(p));
}
__device__ __forceinline__ u64t ffma2(u64t a, u64t b, u64t c) {
    u64t d; asm("fma.rn.f32x2 %0, %1, %2, %3;" : "=l"(d) : "l"(a), "l"(b), "l"(c)); return d;
}
__device__ __forceinline__ u64t mul2(u64t a, u64t b) {
    u64t d; asm("mul.rn.f32x2 %0, %1, %2;" : "=l"(d) : "l"(a), "l"(b)); return d;
}
__device__ __forceinline__ u64t dup2(float v) { return pack2(v, v); }

__device__ __forceinline__ uint32_t smem_u32(const void* p) {
    uint32_t a;
    asm("{ .reg .u64 t; cvta.to.shared.u64 t, %1; cvt.u32.u64 %0, t; }" : "=r"(a) : "l"(p));
    return a;
}
__device__ __forceinline__ void cpa4(uint32_t dst, const float* src) {
    asm volatile("cp.async.ca.shared.global [%0], [%1], 4;" :: "r"(dst), "l"(src));
}
__device__ __forceinline__ void cpa16(uint32_t dst, const float* src) {
    asm volatile("cp.async.cg.shared.global [%0], [%1], 16;" :: "r"(dst), "l"(src));
}
__device__ __forceinline__ void cpa_commit() {
    asm volatile("cp.async.commit_group;" ::: "memory");
}
template <int N>
__device__ __forceinline__ void cpa_wait() {
    asm volatile("cp.async.wait_group %0;" :: "n"(N) : "memory");
}

__device__ __forceinline__ float warp_expsum(float e) {
    float s = e;
    #pragma unroll
    for (int d = 16; d > 0; d >>= 1)
        s += __shfl_xor_sync(0xffffffffu, s, d);
    return s;
}

// PASS=0: c=1/32 (accumulate u straight into s, scale at store); no logits/v.
// PASS=1: b = u.v0 ; store b ; c = softmax(b); s += c*u.
// PASS=2: b = g_b + u.v1 ;     c = softmax(b); s += c*u.
template <int PASS>
__global__ __launch_bounds__(THREADS_, 1)
void pass_kernel(const float* __restrict__ x, const float* __restrict__ W) {
    extern __shared__ char smem_raw[];
    float2* ws  = reinterpret_cast<float2*>(smem_raw);                  // 2 bufs W
    float*  xs  = reinterpret_cast<float*>(smem_raw + WS_BYTES);        // 2 bufs x
    float2* vsm = reinterpret_cast<float2*>(smem_raw + WS_BYTES + XS_BYTES);

    const int tid = threadIdx.x;
    const int w   = tid >> 5;          // warp 0..7
    const int o   = tid & 31;          // lane = out capsule
    const int bx  = blockIdx.x;
    const int bbase = blockIdx.y * 32;
    const int bl0 = w, bl1 = w + 8, bl2 = w + 16, bl3 = w + 24;  // local batches

    const uint32_t ws_u32 = smem_u32(ws);
    const uint32_t xs_u32 = smem_u32(xs);

    // stage v (j-paired float2 in g_v2, linear copy)
    if (PASS > 0) {
        const float2* gv = reinterpret_cast<const float2*>(g_v2) + bbase * (JP_ * OC_);
        #pragma unroll 8
        for (int e = tid; e < VS_F2; e += THREADS_) vsm[e] = gv[e];
    }

    u64t s2[4][JP_];
    #pragma unroll
    for (int b = 0; b < 4; b++)
        #pragma unroll
        for (int jp = 0; jp < JP_; jp++) s2[b][jp] = 0ull;

    // ---- staging: W 4B transpose copies, x 16B copies ----
    auto stage = [&](int buf, int ic) {
        const int i0 = ic * TI_;
        const float* Wb = W + (size_t)i0 * (OC_ * OD_ * ID_);
        const uint32_t wdst_base = ws_u32 + buf * (WBUF_F2 * 8);
        #pragma unroll
        for (int k = 0; k < 64; k++) {
            int f = tid + k * THREADS_;            // 0..16383
            int d = f & 7, j = (f >> 3) & 15, oo = (f >> 7) & 31, il = f >> 12;
            uint32_t dst = wdst_base + (((il * ID_ + d) * WROW_ + (j >> 1) * 33 + oo) << 3)
                         + ((j & 1) << 2);
            cpa4(dst, Wb + f);
        }
        // x: 256 granules of 16B
        {
            int g = tid;
            int b_l = g >> 3, il = (g >> 1) & 3, dh = g & 1;
            const float* src = x + ((size_t)(bbase + b_l) * IC_ + (i0 + il)) * ID_ + dh * 4;
            uint32_t dst = xs_u32 + buf * (XBUF_F * 4) + (((b_l * TI_ + il) * ID_ + dh * 4) << 2);
            cpa16(dst, src);
        }
    };

    // ---- double-buffered chunk loop ----
    int ic = bx;
    stage(0, ic);
    cpa_commit();

    #pragma unroll 1
    for (int k = 0; ic < NCH_; ic += GX_, k++) {
        const int nxt = ic + GX_;
        if (nxt < NCH_) { stage((k + 1) & 1, nxt); cpa_commit(); cpa_wait<1>(); }
        else            { cpa_wait<0>(); }
        __syncthreads();

        const int buf = k & 1;
        const float2* wbuf = ws + buf * WBUF_F2;
        const float*  xbuf = xs + buf * XBUF_F;
        const int i0 = ic * TI_;

        #pragma unroll 1
        for (int il = 0; il < TI_; il++) {
            const int i = i0 + il;
            // x: 8 floats per batch (smem broadcast)
            const float4* xpA = reinterpret_cast<const float4*>(xbuf + (bl0 * TI_ + il) * ID_);
            const float4* xpB = reinterpret_cast<const float4*>(xbuf + (bl1 * TI_ + il) * ID_);
            const float4* xpC = reinterpret_cast<const float4*>(xbuf + (bl2 * TI_ + il) * ID_);
            const float4* xpD = reinterpret_cast<const float4*>(xbuf + (bl3 * TI_ + il) * ID_);
            float xA[8], xB[8], xC[8], xD[8];
            { float4 t0 = xpA[0], t1 = xpA[1];
              xA[0]=t0.x; xA[1]=t0.y; xA[2]=t0.z; xA[3]=t0.w; xA[4]=t1.x; xA[5]=t1.y; xA[6]=t1.z; xA[7]=t1.w; }
            { float4 t0 = xpB[0], t1 = xpB[1];
              xB[0]=t0.x; xB[1]=t0.y; xB[2]=t0.z; xB[3]=t0.w; xB[4]=t1.x; xB[5]=t1.y; xB[6]=t1.z; xB[7]=t1.w; }
            { float4 t0 = xpC[0], t1 = xpC[1];
              xC[0]=t0.x; xC[1]=t0.y; xC[2]=t0.z; xC[3]=t0.w; xC[4]=t1.x; xC[5]=t1.y; xC[6]=t1.z; xC[7]=t1.w; }
            { float4 t0 = xpD[0], t1 = xpD[1];
              xD[0]=t0.x; xD[1]=t0.y; xD[2]=t0.z; xD[3]=t0.w; xD[4]=t1.x; xD[5]=t1.y; xD[6]=t1.z; xD[7]=t1.w; }

            u64t u[4][JP_];

            #pragma unroll
            for (int d = 0; d < ID_; d++) {
                const u64t* wr = reinterpret_cast<const u64t*>(wbuf + (il * ID_ + d) * WROW_ + o);
                u64t wv[JP_];
                #pragma unroll
                for (int jp = 0; jp < JP_; jp++) wv[jp] = wr[jp * 33];   // {W[j],W[j+1]}
                const u64t xdA = dup2(xA[d]), xdB = dup2(xB[d]);
                const u64t xdC = dup2(xC[d]), xdD = dup2(xD[d]);
                if (PASS == 0) {
                    #pragma unroll
                    for (int jp = 0; jp < JP_; jp++) {
                        s2[0][jp] = ffma2(wv[jp], xdA, s2[0][jp]);
                        s2[1][jp] = ffma2(wv[jp], xdB, s2[1][jp]);
                        s2[2][jp] = ffma2(wv[jp], xdC, s2[2][jp]);
                        s2[3][jp] = ffma2(wv[jp], xdD, s2[3][jp]);
                    }
                } else if (d == 0) {
                    #pragma unroll
                    for (int jp = 0; jp < JP_; jp++) {
                        u[0][jp] = mul2(wv[jp], xdA);
                        u[1][jp] = mul2(wv[jp], xdB);
                        u[2][jp] = mul2(wv[jp], xdC);
                        u[3][jp] = mul2(wv[jp], xdD);
                    }
                } else {
                    #pragma unroll
                    for (int jp = 0; jp < JP_; jp++) {
                        u[0][jp] = ffma2(wv[jp], xdA, u[0][jp]);
                        u[1][jp] = ffma2(wv[jp], xdB, u[1][jp]);
                        u[2][jp] = ffma2(wv[jp], xdC, u[2][jp]);
                        u[3][jp] = ffma2(wv[jp], xdD, u[3][jp]);
                    }
                }
            }

            if (PASS > 0) {
                // agreement: two independent chains per batch (ILP)
                u64t agA0 = 0ull, agA1 = 0ull, agB0 = 0ull, agB1 = 0ull;
                u64t agC0 = 0ull, agC1 = 0ull, agD0 = 0ull, agD1 = 0ull;
                const u64t* vb0 = reinterpret_cast<const u64t*>(vsm + bl0 * (JP_ * OC_) + o);
                const u64t* vb1 = reinterpret_cast<const u64t*>(vsm + bl1 * (JP_ * OC_) + o);
                const u64t* vb2 = reinterpret_cast<const u64t*>(vsm + bl2 * (JP_ * OC_) + o);
                const u64t* vb3 = reinterpret_cast<const u64t*>(vsm + bl3 * (JP_ * OC_) + o);
                #pragma unroll
                for (int jp = 0; jp < JP_; jp += 2) {
                    agA0 = ffma2(u[0][jp], vb0[jp * OC_], agA0);
                    agA1 = ffma2(u[0][jp + 1], vb0[(jp + 1) * OC_], agA1);
                    agB0 = ffma2(u[1][jp], vb1[jp * OC_], agB0);
                    agB1 = ffma2(u[1][jp + 1], vb1[(jp + 1) * OC_], agB1);
                    agC0 = ffma2(u[2][jp], vb2[jp * OC_], agC0);
                    agC1 = ffma2(u[2][jp + 1], vb2[(jp + 1) * OC_], agC1);
                    agD0 = ffma2(u[3][jp], vb3[jp * OC_], agD0);
                    agD1 = ffma2(u[3][jp + 1], vb3[(jp + 1) * OC_], agD1);
                }
                float lo, hi, l2, h2, fA, fB, fC, fD;
                unpack2(agA0, lo, hi); unpack2(agA1, l2, h2); fA = (lo + hi) + (l2 + h2);
                unpack2(agB0, lo, hi); unpack2(agB1, l2, h2); fB = (lo + hi) + (l2 + h2);
                unpack2(agC0, lo, hi); unpack2(agC1, l2, h2); fC = (lo + hi) + (l2 + h2);
                unpack2(agD0, lo, hi); unpack2(agD1, l2, h2); fD = (lo + hi) + (l2 + h2);

                const size_t iA = ((size_t)(bbase + bl0) * IC_ + i) * OC_ + o;
                const size_t iB = ((size_t)(bbase + bl1) * IC_ + i) * OC_ + o;
                const size_t iC = ((size_t)(bbase + bl2) * IC_ + i) * OC_ + o;
                const size_t iD = ((size_t)(bbase + bl3) * IC_ + i) * OC_ + o;
                if (PASS == 2) {
                    fA += g_b[iA]; fB += g_b[iB]; fC += g_b[iC]; fD += g_b[iD];
                } else {
                    g_b[iA] = fA; g_b[iB] = fB; g_b[iC] = fC; g_b[iD] = fD;
                }
                const float eA = __expf(fA), eB = __expf(fB), eC = __expf(fC), eD = __expf(fD);
                const float cA = __fdividef(eA, warp_expsum(eA));
                const float cB = __fdividef(eB, warp_expsum(eB));
                const float cC = __fdividef(eC, warp_expsum(eC));
                const float cD = __fdividef(eD, warp_expsum(eD));
                const u64t c2A = dup2(cA), c2B = dup2(cB), c2C = dup2(cC), c2D = dup2(cD);
                #pragma unroll
                for (int jp = 0; jp < JP_; jp++) {
                    s2[0][jp] = ffma2(c2A, u[0][jp], s2[0][jp]);
                    s2[1][jp] = ffma2(c2B, u[1][jp], s2[1][jp]);
                    s2[2][jp] = ffma2(c2C, u[2][jp], s2[2][jp]);
                    s2[3][jp] = ffma2(c2D, u[3][jp], s2[3][jp]);
                }
            }
        }
        __syncthreads();   // all warps done with buf before restage
    }

    // write per-stripe partials: g_spart [stripe][b][o][j]
    {
        const float sc = (PASS == 0) ? (1.0f / 32.0f) : 1.0f;
        const int bls[4] = {bl0, bl1, bl2, bl3};
        #pragma unroll
        for (int b = 0; b < 4; b++) {
            float4* dst = reinterpret_cast<float4*>(
                g_spart + ((size_t)bx * BOD_) + (((bbase + bls[b]) * OC_ + o) * OD_));
            #pragma unroll
            for (int q = 0; q < 4; q++) {
                float l0, h0, l1, h1;
                unpack2(s2[b][2 * q], l0, h0);
                unpack2(s2[b][2 * q + 1], l1, h1);
                dst[q] = make_float4(l0 * sc, h0 * sc, l1 * sc, h1 * sc);
            }
        }
    }
}

// 4-way stripe-split reduce, compile-time 19 stripes/quarter (padded to 76).
template <bool FINAL>
__global__ void reduce_squash(float* __restrict__ out) {
    __shared__ float red[THREADS_];
    const int tid = threadIdx.x;
    const int q = tid >> 6;              // 0..3
    const int el = tid & 63;
    const int e = blockIdx.x * 64 + el;  // global element (b*512 + o*16 + j)

    float s = 0.f;
    const float* p = g_spart + (size_t)(q * 19) * BOD_ + e;
    #pragma unroll
    for (int g = 0; g < 19; g++)
        s += p[(size_t)g * BOD_];

    red[tid] = s;
    __syncthreads();
    if (q == 0) {
        s = red[el] + red[64 + el] + red[128 + el] + red[192 + el];
        float s2 = s * s;
        #pragma unroll
        for (int d = 1; d < 16; d <<= 1)
            s2 += __shfl_xor_sync(0xffffffffu, s2, d);
        const float scale = (s2 / (1.0f + s2)) * rsqrtf(s2 + 1e-9f);
        const float vj = s * scale;
        if (FINAL) {
            out[e] = vj;                              // [b][o][j]
        } else {
            const int j = e & 15, bo = e >> 4, b = bo >> 5, oo = bo & 31;
            g_v2[(((b * JP_ + (j >> 1)) * OC_) + oo) * 2 + (j & 1)] = vj;
        }
    }
}

extern "C" void kernel_launch(void* const* d_in, const int* in_sizes, int n_in,
                              void* d_out, int out_size) {
    const float* x = (const float*)d_in[0];   // [64, 2048, 8]
    const float* W = (const float*)d_in[1];   // [1, 2048, 32, 16, 8]
    float* out = (float*)d_out;               // [64, 32, 16]
    (void)in_sizes; (void)n_in; (void)out_size;

    static bool attr_done = false;
    if (!attr_done) {
        cudaFuncSetAttribute(pass_kernel<0>, cudaFuncAttributeMaxDynamicSharedMemorySize, SMEM_BYTES);
        cudaFuncSetAttribute(pass_kernel<1>, cudaFuncAttributeMaxDynamicSharedMemorySize, SMEM_BYTES);
        cudaFuncSetAttribute(pass_kernel<2>, cudaFuncAttributeMaxDynamicSharedMemorySize, SMEM_BYTES);
        attr_done = true;
    }

    const dim3 grid(GX_, 2);
    const dim3 rgrid(BOD_ / 64);              // 512 blocks

    pass_kernel<0><<<grid, THREADS_, SMEM_BYTES>>>(x, W);
    reduce_squash<false><<<rgrid, THREADS_>>>(nullptr);   // v0 -> g_v2
    pass_kernel<1><<<grid, THREADS_, SMEM_BYTES>>>(x, W);
    reduce_squash<false><<<rgrid, THREADS_>>>(nullptr);   // v1 -> g_v2
    pass_kernel<2><<<grid, THREADS_, SMEM_BYTES>>>(x, W);
    reduce_squash<true><<<rgrid, THREADS_>>>(out);        // v2 -> d_out
}

// round 13
// speedup vs baseline: 1.5817x; 1.5817x over previous
#include <cuda_runtime.h>
#include <cstdint>

// CapsNet dynamic routing, B=64, IC=2048, ID=8, OC=32, OD=16, 3 routing iters.
// R13 = R9 pass kernel VERBATIM (measured 35us/pass; R12's agreement-chain
//       split is reverted — suspected register-spill regression) + R12
//       reduce_squash (measured 7us; padded 76 stripes, compile-time 19/quarter).

#define B_      64
#define IC_     2048
#define ID_     8
#define OC_     32
#define OD_     16
#define TI_     4              // i's per smem chunk
#define NCH_    (IC_ / TI_)    // 512 chunks
#define GX_     74             // i-stripe blocks; grid (74,2) = 148 = one wave
#define GXP_    76             // padded stripe count (74,75 stay zero)
#define THREADS_ 256
#define JP_     8              // j pairs
#define BOD_    (B_ * OC_ * OD_)   // 32768
#define WROW_   265            // float2 stride per (il,d): 8*33+1

typedef unsigned long long u64t;

// ---- device scratch (allocation-free; zero-initialized) ----
__device__ float g_b[B_ * IC_ * OC_];              // routing logits (16.7MB)
__device__ float g_spart[GXP_ * BOD_];             // per-stripe partial s (9.96MB)
__device__ float g_v2[B_ * JP_ * OC_ * 2];         // v j-paired [b][jp][o]{j0,j1}

// ---- shared memory layout (bytes) ----
#define WBUF_F2   (TI_ * ID_ * WROW_)              // 8480 float2 = 67840 B per buffer
#define WS_BYTES  (2 * WBUF_F2 * 8)                // 135680
#define XBUF_F    (32 * TI_ * ID_)                 // 1024 floats per buffer
#define XS_BYTES  (2 * XBUF_F * 4)                 // 8192
#define VS_F2     (32 * JP_ * OC_)                 // 8192 float2 = 65536 B
#define SMEM_BYTES (WS_BYTES + XS_BYTES + VS_F2 * 8)   // 209408

// ---- f32x2 helpers ----
__device__ __forceinline__ u64t pack2(float lo, float hi) {
    u64t r; asm("mov.b64 %0, {%1, %2};" : "=l"(r) : "f"(lo), "f"(hi)); return r;
}
__device__ __forceinline__ void unpack2(u64t p, float& lo, float& hi) {
    asm("mov.b64 {%0, %1}, %2;" : "=f"(lo), "=f"(hi) : "l"(p));
}
__device__ __forceinline__ u64t ffma2(u64t a, u64t b, u64t c) {
    u64t d; asm("fma.rn.f32x2 %0, %1, %2, %3;" : "=l"(d) : "l"(a), "l"(b), "l"(c)); return d;
}
__device__ __forceinline__ u64t mul2(u64t a, u64t b) {
    u64t d; asm("mul.rn.f32x2 %0, %1, %2;" : "=l"(d) : "l"(a), "l"(b)); return d;
}
__device__ __forceinline__ u64t dup2(float v) { return pack2(v, v); }

__device__ __forceinline__ uint32_t smem_u32(const void* p) {
    uint32_t a;
    asm("{ .reg .u64 t; cvta.to.shared.u64 t, %1; cvt.u32.u64 %0, t; }" : "=r"(a) : "l"(p));
    return a;
}
__device__ __forceinline__ void cpa4(uint32_t dst, const float* src) {
    asm volatile("cp.async.ca.shared.global [%0], [%1], 4;" :: "r"(dst), "l"(src));
}
__device__ __forceinline__ void cpa16(uint32_t dst, const float* src) {
    asm volatile("cp.async.cg.shared.global [%0], [%1], 16;" :: "r"(dst), "l"(src));
}
__device__ __forceinline__ void cpa_commit() {
    asm volatile("cp.async.commit_group;" ::: "memory");
}
template <int N>
__device__ __forceinline__ void cpa_wait() {
    asm volatile("cp.async.wait_group %0;" :: "n"(N) : "memory");
}

__device__ __forceinline__ float warp_expsum(float e) {
    float s = e;
    #pragma unroll
    for (int d = 16; d > 0; d >>= 1)
        s += __shfl_xor_sync(0xffffffffu, s, d);
    return s;
}

// PASS=0: c=1/32 (accumulate u straight into s, scale at store); no logits/v.
// PASS=1: b = u.v0 ; store b ; c = softmax(b); s += c*u.
// PASS=2: b = g_b + u.v1 ;     c = softmax(b); s += c*u.
template <int PASS>
__global__ __launch_bounds__(THREADS_, 1)
void pass_kernel(const float* __restrict__ x, const float* __restrict__ W) {
    extern __shared__ char smem_raw[];
    float2* ws  = reinterpret_cast<float2*>(smem_raw);                  // 2 bufs W
    float*  xs  = reinterpret_cast<float*>(smem_raw + WS_BYTES);        // 2 bufs x
    float2* vsm = reinterpret_cast<float2*>(smem_raw + WS_BYTES + XS_BYTES);

    const int tid = threadIdx.x;
    const int w   = tid >> 5;          // warp 0..7
    const int o   = tid & 31;          // lane = out capsule
    const int bx  = blockIdx.x;
    const int bbase = blockIdx.y * 32;
    const int bl0 = w, bl1 = w + 8, bl2 = w + 16, bl3 = w + 24;  // local batches

    const uint32_t ws_u32 = smem_u32(ws);
    const uint32_t xs_u32 = smem_u32(xs);

    // stage v (j-paired float2 in g_v2, linear copy)
    if (PASS > 0) {
        const float2* gv = reinterpret_cast<const float2*>(g_v2) + bbase * (JP_ * OC_);
        #pragma unroll 8
        for (int e = tid; e < VS_F2; e += THREADS_) vsm[e] = gv[e];
    }

    u64t s2[4][JP_];
    #pragma unroll
    for (int b = 0; b < 4; b++)
        #pragma unroll
        for (int jp = 0; jp < JP_; jp++) s2[b][jp] = 0ull;

    // ---- staging: W 4B transpose copies, x 16B copies ----
    auto stage = [&](int buf, int ic) {
        const int i0 = ic * TI_;
        const float* Wb = W + (size_t)i0 * (OC_ * OD_ * ID_);
        const uint32_t wdst_base = ws_u32 + buf * (WBUF_F2 * 8);
        #pragma unroll
        for (int k = 0; k < 64; k++) {
            int f = tid + k * THREADS_;            // 0..16383
            int d = f & 7, j = (f >> 3) & 15, oo = (f >> 7) & 31, il = f >> 12;
            uint32_t dst = wdst_base + (((il * ID_ + d) * WROW_ + (j >> 1) * 33 + oo) << 3)
                         + ((j & 1) << 2);
            cpa4(dst, Wb + f);
        }
        // x: 256 granules of 16B
        {
            int g = tid;
            int b_l = g >> 3, il = (g >> 1) & 3, dh = g & 1;
            const float* src = x + ((size_t)(bbase + b_l) * IC_ + (i0 + il)) * ID_ + dh * 4;
            uint32_t dst = xs_u32 + buf * (XBUF_F * 4) + (((b_l * TI_ + il) * ID_ + dh * 4) << 2);
            cpa16(dst, src);
        }
    };

    // ---- double-buffered chunk loop ----
    int ic = bx;
    stage(0, ic);
    cpa_commit();

    #pragma unroll 1
    for (int k = 0; ic < NCH_; ic += GX_, k++) {
        const int nxt = ic + GX_;
        if (nxt < NCH_) { stage((k + 1) & 1, nxt); cpa_commit(); cpa_wait<1>(); }
        else            { cpa_wait<0>(); }
        __syncthreads();

        const int buf = k & 1;
        const float2* wbuf = ws + buf * WBUF_F2;
        const float*  xbuf = xs + buf * XBUF_F;
        const int i0 = ic * TI_;

        #pragma unroll 1
        for (int il = 0; il < TI_; il++) {
            const int i = i0 + il;
            // x: 8 floats per batch (smem broadcast)
            const float4* xpA = reinterpret_cast<const float4*>(xbuf + (bl0 * TI_ + il) * ID_);
            const float4* xpB = reinterpret_cast<const float4*>(xbuf + (bl1 * TI_ + il) * ID_);
            const float4* xpC = reinterpret_cast<const float4*>(xbuf + (bl2 * TI_ + il) * ID_);
            const float4* xpD = reinterpret_cast<const float4*>(xbuf + (bl3 * TI_ + il) * ID_);
            float xA[8], xB[8], xC[8], xD[8];
            { float4 t0 = xpA[0], t1 = xpA[1];
              xA[0]=t0.x; xA[1]=t0.y; xA[2]=t0.z; xA[3]=t0.w; xA[4]=t1.x; xA[5]=t1.y; xA[6]=t1.z; xA[7]=t1.w; }
            { float4 t0 = xpB[0], t1 = xpB[1];
              xB[0]=t0.x; xB[1]=t0.y; xB[2]=t0.z; xB[3]=t0.w; xB[4]=t1.x; xB[5]=t1.y; xB[6]=t1.z; xB[7]=t1.w; }
            { float4 t0 = xpC[0], t1 = xpC[1];
              xC[0]=t0.x; xC[1]=t0.y; xC[2]=t0.z; xC[3]=t0.w; xC[4]=t1.x; xC[5]=t1.y; xC[6]=t1.z; xC[7]=t1.w; }
            { float4 t0 = xpD[0], t1 = xpD[1];
              xD[0]=t0.x; xD[1]=t0.y; xD[2]=t0.z; xD[3]=t0.w; xD[4]=t1.x; xD[5]=t1.y; xD[6]=t1.z; xD[7]=t1.w; }

            u64t u[4][JP_];

            #pragma unroll
            for (int d = 0; d < ID_; d++) {
                const u64t* wr = reinterpret_cast<const u64t*>(wbuf + (il * ID_ + d) * WROW_ + o);
                u64t wv[JP_];
                #pragma unroll
                for (int jp = 0; jp < JP_; jp++) wv[jp] = wr[jp * 33];   // {W[j],W[j+1]}
                const u64t xdA = dup2(xA[d]), xdB = dup2(xB[d]);
                const u64t xdC = dup2(xC[d]), xdD = dup2(xD[d]);
                if (PASS == 0) {
                    #pragma unroll
                    for (int jp = 0; jp < JP_; jp++) {
                        s2[0][jp] = ffma2(wv[jp], xdA, s2[0][jp]);
                        s2[1][jp] = ffma2(wv[jp], xdB, s2[1][jp]);
                        s2[2][jp] = ffma2(wv[jp], xdC, s2[2][jp]);
                        s2[3][jp] = ffma2(wv[jp], xdD, s2[3][jp]);
                    }
                } else if (d == 0) {
                    #pragma unroll
                    for (int jp = 0; jp < JP_; jp++) {
                        u[0][jp] = mul2(wv[jp], xdA);
                        u[1][jp] = mul2(wv[jp], xdB);
                        u[2][jp] = mul2(wv[jp], xdC);
                        u[3][jp] = mul2(wv[jp], xdD);
                    }
                } else {
                    #pragma unroll
                    for (int jp = 0; jp < JP_; jp++) {
                        u[0][jp] = ffma2(wv[jp], xdA, u[0][jp]);
                        u[1][jp] = ffma2(wv[jp], xdB, u[1][jp]);
                        u[2][jp] = ffma2(wv[jp], xdC, u[2][jp]);
                        u[3][jp] = ffma2(wv[jp], xdD, u[3][jp]);
                    }
                }
            }

            if (PASS > 0) {
                // agreement: b_upd = sum_j u*v (paired) — single chain per batch
                u64t ag0 = 0ull, ag1 = 0ull, ag2 = 0ull, ag3 = 0ull;
                const u64t* vb0 = reinterpret_cast<const u64t*>(vsm + bl0 * (JP_ * OC_) + o);
                const u64t* vb1 = reinterpret_cast<const u64t*>(vsm + bl1 * (JP_ * OC_) + o);
                const u64t* vb2 = reinterpret_cast<const u64t*>(vsm + bl2 * (JP_ * OC_) + o);
                const u64t* vb3 = reinterpret_cast<const u64t*>(vsm + bl3 * (JP_ * OC_) + o);
                #pragma unroll
                for (int jp = 0; jp < JP_; jp++) {
                    ag0 = ffma2(u[0][jp], vb0[jp * OC_], ag0);
                    ag1 = ffma2(u[1][jp], vb1[jp * OC_], ag1);
                    ag2 = ffma2(u[2][jp], vb2[jp * OC_], ag2);
                    ag3 = ffma2(u[3][jp], vb3[jp * OC_], ag3);
                }
                float lo, hi, fA, fB, fC, fD;
                unpack2(ag0, lo, hi); fA = lo + hi;
                unpack2(ag1, lo, hi); fB = lo + hi;
                unpack2(ag2, lo, hi); fC = lo + hi;
                unpack2(ag3, lo, hi); fD = lo + hi;

                const size_t iA = ((size_t)(bbase + bl0) * IC_ + i) * OC_ + o;
                const size_t iB = ((size_t)(bbase + bl1) * IC_ + i) * OC_ + o;
                const size_t iC = ((size_t)(bbase + bl2) * IC_ + i) * OC_ + o;
                const size_t iD = ((size_t)(bbase + bl3) * IC_ + i) * OC_ + o;
                if (PASS == 2) {
                    fA += g_b[iA]; fB += g_b[iB]; fC += g_b[iC]; fD += g_b[iD];
                } else {
                    g_b[iA] = fA; g_b[iB] = fB; g_b[iC] = fC; g_b[iD] = fD;
                }
                const float eA = __expf(fA), eB = __expf(fB), eC = __expf(fC), eD = __expf(fD);
                const float cA = __fdividef(eA, warp_expsum(eA));
                const float cB = __fdividef(eB, warp_expsum(eB));
                const float cC = __fdividef(eC, warp_expsum(eC));
                const float cD = __fdividef(eD, warp_expsum(eD));
                const u64t c2A = dup2(cA), c2B = dup2(cB), c2C = dup2(cC), c2D = dup2(cD);
                #pragma unroll
                for (int jp = 0; jp < JP_; jp++) {
                    s2[0][jp] = ffma2(c2A, u[0][jp], s2[0][jp]);
                    s2[1][jp] = ffma2(c2B, u[1][jp], s2[1][jp]);
                    s2[2][jp] = ffma2(c2C, u[2][jp], s2[2][jp]);
                    s2[3][jp] = ffma2(c2D, u[3][jp], s2[3][jp]);
                }
            }
        }
        __syncthreads();   // all warps done with buf before restage
    }

    // write per-stripe partials: g_spart [stripe][b][o][j]
    {
        const float sc = (PASS == 0) ? (1.0f / 32.0f) : 1.0f;
        const int bls[4] = {bl0, bl1, bl2, bl3};
        #pragma unroll
        for (int b = 0; b < 4; b++) {
            float4* dst = reinterpret_cast<float4*>(
                g_spart + (((size_t)bx * B_ + (bbase + bls[b])) * OC_ + o) * OD_);
            #pragma unroll
            for (int q = 0; q < 4; q++) {
                float l0, h0, l1, h1;
                unpack2(s2[b][2 * q], l0, h0);
                unpack2(s2[b][2 * q + 1], l1, h1);
                dst[q] = make_float4(l0 * sc, h0 * sc, l1 * sc, h1 * sc);
            }
        }
    }
}

// 4-way stripe-split reduce, compile-time 19 stripes/quarter (padded to 76).
template <bool FINAL>
__global__ void reduce_squash(float* __restrict__ out) {
    __shared__ float red[THREADS_];
    const int tid = threadIdx.x;
    const int q = tid >> 6;              // 0..3
    const int el = tid & 63;
    const int e = blockIdx.x * 64 + el;  // global element (b*512 + o*16 + j)

    float s = 0.f;
    const float* p = g_spart + (size_t)(q * 19) * BOD_ + e;
    #pragma unroll
    for (int g = 0; g < 19; g++)
        s += p[(size_t)g * BOD_];

    red[tid] = s;
    __syncthreads();
    if (q == 0) {
        s = red[el] + red[64 + el] + red[128 + el] + red[192 + el];
        float s2 = s * s;
        #pragma unroll
        for (int d = 1; d < 16; d <<= 1)
            s2 += __shfl_xor_sync(0xffffffffu, s2, d);
        const float scale = (s2 / (1.0f + s2)) * rsqrtf(s2 + 1e-9f);
        const float vj = s * scale;
        if (FINAL) {
            out[e] = vj;                              // [b][o][j]
        } else {
            const int j = e & 15, bo = e >> 4, b = bo >> 5, oo = bo & 31;
            g_v2[(((b * JP_ + (j >> 1)) * OC_) + oo) * 2 + (j & 1)] = vj;
        }
    }
}

extern "C" void kernel_launch(void* const* d_in, const int* in_sizes, int n_in,
                              void* d_out, int out_size) {
    const float* x = (const float*)d_in[0];   // [64, 2048, 8]
    const float* W = (const float*)d_in[1];   // [1, 2048, 32, 16, 8]
    float* out = (float*)d_out;               // [64, 32, 16]
    (void)in_sizes; (void)n_in; (void)out_size;

    static bool attr_done = false;
    if (!attr_done) {
        cudaFuncSetAttribute(pass_kernel<0>, cudaFuncAttributeMaxDynamicSharedMemorySize, SMEM_BYTES);
        cudaFuncSetAttribute(pass_kernel<1>, cudaFuncAttributeMaxDynamicSharedMemorySize, SMEM_BYTES);
        cudaFuncSetAttribute(pass_kernel<2>, cudaFuncAttributeMaxDynamicSharedMemorySize, SMEM_BYTES);
        attr_done = true;
    }

    const dim3 grid(GX_, 2);
    const dim3 rgrid(BOD_ / 64);              // 512 blocks

    pass_kernel<0><<<grid, THREADS_, SMEM_BYTES>>>(x, W);
    reduce_squash<false><<<rgrid, THREADS_>>>(nullptr);   // v0 -> g_v2
    pass_kernel<1><<<grid, THREADS_, SMEM_BYTES>>>(x, W);
    reduce_squash<false><<<rgrid, THREADS_>>>(nullptr);   // v1 -> g_v2
    pass_kernel<2><<<grid, THREADS_, SMEM_BYTES>>>(x, W);
    reduce_squash<true><<<rgrid, THREADS_>>>(out);        // v2 -> d_out
}